// round 9
// baseline (speedup 1.0000x reference)
#include <cuda_runtime.h>
#include <cuda_fp16.h>
#include <cstdint>

// ---------------------------------------------------------------------------
// out = concat( relu(A@relu(A@F)), A@(A@G) ), A:[8192,8192] f32, F,G:[8192,64]
// Per layer: fused GEMM C[8192,128] = A @ Bt^T, relu on cols [0,64).
// fp16 mma.m16n8k16. 8 MMA warps (2/SMSP, 32x32 tiles). A loaded DIRECTLY from
// GMEM into registers (float2 per-lane fragment pattern, L1-shared across the
// 4 wn-warps), scaled x2^13 + packed fp16x2 in-register, one stage ahead.
// Shared memory carries only B (cp.async, 8KB/stage) -> crossbar ~24KB/stage.
// ---------------------------------------------------------------------------

#define NN      8192
#define NB      128
#define MT      64              // M rows per CTA -> 128 CTAs
#define KT      32              // K per stage
#define STAGES  4
#define KIT     (NN / KT)       // 256
#define B_PITCH 64              // bytes per B smem row (fp16 k32)
#define B_STG_B (128 * B_PITCH) // 8192
#define SMEM_BYTES (STAGES * B_STG_B)      // 32768

__device__ __half g_bth1[NB * NN];   // layer-1 B, fp16 chunk-permuted
__device__ __half g_bth2[NB * NN];   // layer-1 out (x2^6) = layer-2 B

// chunk permutation within each k32 block (2-element chunks):
// chunk j -> position (j%4)*4 + j/4
__device__ __forceinline__ int kperm2(int k) {
    int j = (k >> 1) & 15;
    int p = ((j & 3) << 2) | (j >> 2);
    return (k & ~31) | (p << 1) | (k & 1);
}

__device__ __forceinline__ uint32_t smem_u32(const void* p) {
    uint32_t a;
    asm("{ .reg .u64 t; cvta.to.shared.u64 t, %1; cvt.u32.u64 %0, t; }"
        : "=r"(a) : "l"(p));
    return a;
}

// pack two fp32 -> fp16x2 (lo = first arg)
__device__ __forceinline__ uint32_t pack_h2(float lo, float hi) {
    uint32_t d;
    asm("cvt.rn.f16x2.f32 %0, %1, %2;" : "=r"(d) : "f"(hi), "f"(lo));
    return d;
}

#define CP_ASYNC16(dst, src) \
    asm volatile("cp.async.cg.shared.global [%0], [%1], 16;" \
                 :: "r"(dst), "l"(src) : "memory")
#define CP_COMMIT() asm volatile("cp.async.commit_group;" ::: "memory")
#define CP_WAIT2()  asm volatile("cp.async.wait_group 2;" ::: "memory")

__device__ __forceinline__ void mma_f16(float* c, const uint32_t* a,
                                        uint32_t b0, uint32_t b1) {
    asm volatile(
        "mma.sync.aligned.m16n8k16.row.col.f32.f16.f16.f32 "
        "{%0,%1,%2,%3}, {%4,%5,%6,%7}, {%8,%9}, {%0,%1,%2,%3};"
        : "+f"(c[0]), "+f"(c[1]), "+f"(c[2]), "+f"(c[3])
        : "r"(a[0]), "r"(a[1]), "r"(a[2]), "r"(a[3]), "r"(b0), "r"(b1));
}

// ---------------------------------------------------------------------------
__global__ void pack_bt_kernel(const float* __restrict__ F,
                               const float* __restrict__ G,
                               __half* __restrict__ Bt) {
    __shared__ float tile[32][33];
    int kb = blockIdx.x * 32;
    int nb = blockIdx.y * 32;
    int tx = threadIdx.x, ty = threadIdx.y;   // block (32, 8)
    #pragma unroll
    for (int r = ty; r < 32; r += 8) {
        int k = kb + r, n = nb + tx;
        float v = (n < 64) ? F[(size_t)k * 64 + n] : G[(size_t)k * 64 + (n - 64)];
        tile[r][tx] = v;
    }
    __syncthreads();
    #pragma unroll
    for (int r = ty; r < 32; r += 8) {
        int n = nb + r, k = kb + tx;
        Bt[(size_t)n * NN + kperm2(k)] = __float2half_rn(tile[tx][r]);
    }
}

// ---------------------------------------------------------------------------
__global__ void __launch_bounds__(256, 1)
gemm_layer(const float* __restrict__ A, const __half* __restrict__ Bt,
           __half* __restrict__ outT, float* __restrict__ outR, float scale) {
    extern __shared__ char smem[];

    const int tid  = threadIdx.x;
    const int lane = tid & 31;
    const int w    = tid >> 5;           // 8 warps, all consumers
    const int m0   = blockIdx.x * MT;
    const uint32_t sbase = smem_u32(smem);
    const int r4 = lane >> 2;
    const int c4 = lane & 3;

    const int wm = w & 1;                // rows wm*32 .. +31
    const int wn = w >> 1;               // cols wn*32 .. +31

    float acc[2][4][4];
    #pragma unroll
    for (int mi = 0; mi < 2; mi++)
        #pragma unroll
        for (int ni = 0; ni < 4; ni++)
            #pragma unroll
            for (int j = 0; j < 4; j++) acc[mi][ni][j] = 0.f;

    // B producer: every thread contributes 2 x 16B per stage
    auto cpB = [&](int it) {
        const int k0 = it * KT;
        const uint32_t bbase = sbase + (uint32_t)(it & (STAGES - 1)) * B_STG_B;
        #pragma unroll
        for (int j = 0; j < 2; j++) {
            int ch = tid + 256 * j;
            int col = ch >> 2, q = ch & 3;
            const __half* src = Bt + (size_t)col * NN + k0 + q * 8;
            CP_ASYNC16(bbase + (uint32_t)(col * B_PITCH + q * 16), src);
        }
    };

    // Per-thread A base pointers (fragment pattern), rows r4+8g
    const float* aRow[4];
    #pragma unroll
    for (int g = 0; g < 4; g++)
        aRow[g] = A + (size_t)(m0 + wm * 32 + r4 + 8 * g) * NN + 2 * c4;

    // raw A stage buffer: [g][h][j] j: ksub (+0 / +8)
    float2 raw[4][2][2];
    auto ldgA = [&](int it) {
        const int k0 = it * KT;
        #pragma unroll
        for (int g = 0; g < 4; g++)
            #pragma unroll
            for (int h = 0; h < 2; h++)
                #pragma unroll
                for (int j = 0; j < 2; j++)
                    raw[g][h][j] =
                        *(const float2*)(aRow[g] + k0 + 16 * h + 8 * j);
    };
    auto cvtA = [&](uint32_t (&pk)[4][2][2]) {
        #pragma unroll
        for (int g = 0; g < 4; g++)
            #pragma unroll
            for (int h = 0; h < 2; h++)
                #pragma unroll
                for (int j = 0; j < 2; j++)
                    pk[g][h][j] = pack_h2(raw[g][h][j].x * 8192.f,
                                          raw[g][h][j].y * 8192.f);
    };

    const uint32_t boff = (uint32_t)((wn * 32 + r4) * B_PITCH + 16 * c4);

    uint32_t aPk[2][4][2][2];

    // prologue
    cpB(0); CP_COMMIT();
    cpB(1); CP_COMMIT();
    cpB(2); CP_COMMIT();
    ldgA(0);
    cvtA(aPk[0]);

    for (int it = 0; it < KIT; it++) {
        const int s = it & (STAGES - 1);
        const int cur = it & 1, nxt = cur ^ 1;

        CP_WAIT2();
        __syncthreads();                 // B(it) resident, B(it-? ) reusable
        if (it + 3 < KIT) cpB(it + 3);
        CP_COMMIT();

        // B frags: 4 n8-groups, uint4 covers k32
        const uint32_t bb = sbase + (uint32_t)s * B_STG_B + boff;
        uint4 bFr[4];
        #pragma unroll
        for (int n = 0; n < 4; n++) {
            asm volatile("ld.shared.v4.b32 {%0, %1, %2, %3}, [%4];"
                         : "=r"(bFr[n].x), "=r"(bFr[n].y),
                           "=r"(bFr[n].z), "=r"(bFr[n].w)
                         : "r"(bb + (uint32_t)(n * 8 * B_PITCH)));
        }

        if (it + 1 < KIT) ldgA(it + 1);  // LDG issues; hides under burst

        #pragma unroll
        for (int h = 0; h < 2; h++) {
            #pragma unroll
            for (int mi = 0; mi < 2; mi++) {
                uint32_t af[4] = { aPk[cur][2 * mi][h][0],
                                   aPk[cur][2 * mi + 1][h][0],
                                   aPk[cur][2 * mi][h][1],
                                   aPk[cur][2 * mi + 1][h][1] };
                #pragma unroll
                for (int n = 0; n < 4; n++) {
                    uint32_t b0 = h ? bFr[n].z : bFr[n].x;
                    uint32_t b1 = h ? bFr[n].w : bFr[n].y;
                    mma_f16(acc[mi][n], af, b0, b1);
                }
            }
        }

        if (it + 1 < KIT) cvtA(aPk[nxt]);
    }

    // ---- epilogue ----
    const int rBase = m0 + wm * 32 + r4;
    const int cBase = wn * 32 + c4 * 2;
    #pragma unroll
    for (int mi = 0; mi < 2; mi++) {
        #pragma unroll
        for (int ni = 0; ni < 4; ni++) {
            #pragma unroll
            for (int j = 0; j < 4; j++) {
                int row = rBase + mi * 16 + (j >> 1) * 8;
                int col = cBase + ni * 8 + (j & 1);
                float v = acc[mi][ni][j] * scale;
                if (col < 64) v = fmaxf(v, 0.0f);
                if (outT) outT[(size_t)col * NN + kperm2(row)] = __float2half_rn(v);
                else      outR[(size_t)row * NB + col] = v;
            }
        }
    }
}

// ---------------------------------------------------------------------------
extern "C" void kernel_launch(void* const* d_in, const int* in_sizes, int n_in,
                              void* d_out, int out_size) {
    (void)in_sizes; (void)n_in; (void)out_size;
    const float* A = (const float*)d_in[0];
    const float* F = (const float*)d_in[1];
    const float* G = (const float*)d_in[2];
    float* out = (float*)d_out;

    __half *bt1 = nullptr, *bt2 = nullptr;
    cudaGetSymbolAddress((void**)&bt1, g_bth1);
    cudaGetSymbolAddress((void**)&bt2, g_bth2);

    cudaFuncSetAttribute(gemm_layer,
                         cudaFuncAttributeMaxDynamicSharedMemorySize, SMEM_BYTES);

    dim3 pb(32, 8), pg(NN / 32, NB / 32);
    pack_bt_kernel<<<pg, pb>>>(F, G, bt1);

    // layer 1: acc = (2^13 A) @ B ; store fp16( acc * 2^-7 ) = 2^6 * (A@B)
    gemm_layer<<<NN / MT, 256, SMEM_BYTES>>>(A, bt1, bt2, nullptr, 0.0078125f);
    // layer 2: acc = (2^13 A) @ (2^6 h) ; out = acc * 2^-19
    gemm_layer<<<NN / MT, 256, SMEM_BYTES>>>(A, bt2, nullptr, out,
                                             1.0f / 524288.0f);
}

// round 10
// speedup vs baseline: 4.2442x; 4.2442x over previous
#include <cuda_runtime.h>
#include <cuda_fp16.h>
#include <cstdint>

// ---------------------------------------------------------------------------
// out = concat( relu(A@relu(A@F)), A@(A@G) ), A:[8192,8192] f32, F,G:[8192,64]
// Per layer: fused GEMM C[8192,128] = A @ Bt^T, relu on cols [0,64).
// fp16 mma.m16n8k16; 4 producer warps (cp.async A fp32 + B fp16) + 4 MMA
// warps (32x64 reg tiles). KT=64 stages consumed as two k32 blocks with
// register double-buffering; barrier overhead amortized over 1024 tensor cyc.
// ---------------------------------------------------------------------------

#define NN      8192
#define NB      128
#define MT      64               // M rows per CTA -> 128 CTAs
#define KT      64               // K per stage
#define STAGES  4
#define KIT     (NN / KT)        // 128
#define A_PITCH 288              // bytes per A smem row (72 words, %32==8)
#define A_STG_B (64 * A_PITCH)   // 18432
#define B_PLANE 8192             // 128 cols x 64B (one k32 plane)
#define B_STG_B (2 * B_PLANE)    // 16384
#define STG_B   (A_STG_B + B_STG_B)        // 34816
#define SMEM_BYTES (STAGES * STG_B)        // 139264

__device__ __half g_bth1[NB * NN];   // layer-1 B, fp16 chunk-permuted
__device__ __half g_bth2[NB * NN];   // layer-1 out (x2^6) = layer-2 B

// chunk permutation within each k32 block (2-element chunks):
// chunk j -> position (j%4)*4 + j/4
__device__ __forceinline__ int kperm2(int k) {
    int j = (k >> 1) & 15;
    int p = ((j & 3) << 2) | (j >> 2);
    return (k & ~31) | (p << 1) | (k & 1);
}

__device__ __forceinline__ uint32_t smem_u32(const void* p) {
    uint32_t a;
    asm("{ .reg .u64 t; cvta.to.shared.u64 t, %1; cvt.u32.u64 %0, t; }"
        : "=r"(a) : "l"(p));
    return a;
}

// pack two fp32 -> fp16x2 (lo = first arg)
__device__ __forceinline__ uint32_t pack_h2(float lo, float hi) {
    uint32_t d;
    asm("cvt.rn.f16x2.f32 %0, %1, %2;" : "=r"(d) : "f"(hi), "f"(lo));
    return d;
}

#define CP_ASYNC16(dst, src) \
    asm volatile("cp.async.cg.shared.global [%0], [%1], 16;" \
                 :: "r"(dst), "l"(src) : "memory")

#define MBAR_INIT(addr, cnt) \
    asm volatile("mbarrier.init.shared.b64 [%0], %1;" :: "r"(addr), "r"(cnt) : "memory")
#define MBAR_ARRIVE(addr) \
    asm volatile("mbarrier.arrive.shared.b64 _, [%0];" :: "r"(addr) : "memory")
#define CP_ASYNC_MBAR_ARRIVE(addr) \
    asm volatile("cp.async.mbarrier.arrive.noinc.shared::cta.b64 [%0];" \
                 :: "r"(addr) : "memory")

#define MBAR_WAIT(addr, parity) do {                                          \
    uint32_t _mb = (addr); uint32_t _ph = (parity); uint32_t _done;           \
    asm volatile("{\n\t.reg .pred p;\n\t"                                     \
        "mbarrier.try_wait.parity.acquire.cta.shared::cta.b64 p, [%1], %2;\n\t"\
        "selp.b32 %0, 1, 0, p;\n\t}"                                          \
        : "=r"(_done) : "r"(_mb), "r"(_ph) : "memory");                       \
    if (!_done) {                                                             \
        asm volatile("{\n\t.reg .pred P1;\n\t"                                \
            "WL_%=:\n\t"                                                      \
            "mbarrier.try_wait.parity.acquire.cta.shared::cta.b64 P1, [%0], %1, 0x989680;\n\t" \
            "@P1 bra.uni WD_%=;\n\t"                                          \
            "bra.uni WL_%=;\n\t"                                              \
            "WD_%=:\n\t}"                                                     \
            :: "r"(_mb), "r"(_ph) : "memory");                                \
    }                                                                         \
} while (0)

__device__ __forceinline__ void mma_f16(float* c, const uint32_t* a,
                                        uint32_t b0, uint32_t b1) {
    asm volatile(
        "mma.sync.aligned.m16n8k16.row.col.f32.f16.f16.f32 "
        "{%0,%1,%2,%3}, {%4,%5,%6,%7}, {%8,%9}, {%0,%1,%2,%3};"
        : "+f"(c[0]), "+f"(c[1]), "+f"(c[2]), "+f"(c[3])
        : "r"(a[0]), "r"(a[1]), "r"(a[2]), "r"(a[3]), "r"(b0), "r"(b1));
}

// ---------------------------------------------------------------------------
__global__ void pack_bt_kernel(const float* __restrict__ F,
                               const float* __restrict__ G,
                               __half* __restrict__ Bt) {
    __shared__ float tile[32][33];
    int kb = blockIdx.x * 32;
    int nb = blockIdx.y * 32;
    int tx = threadIdx.x, ty = threadIdx.y;   // block (32, 8)
    #pragma unroll
    for (int r = ty; r < 32; r += 8) {
        int k = kb + r, n = nb + tx;
        float v = (n < 64) ? F[(size_t)k * 64 + n] : G[(size_t)k * 64 + (n - 64)];
        tile[r][tx] = v;
    }
    __syncthreads();
    #pragma unroll
    for (int r = ty; r < 32; r += 8) {
        int n = nb + r, k = kb + tx;
        Bt[(size_t)n * NN + kperm2(k)] = __float2half_rn(tile[tx][r]);
    }
}

// ---------------------------------------------------------------------------
__global__ void __launch_bounds__(256, 1)
gemm_layer(const float* __restrict__ A, const __half* __restrict__ Bt,
           __half* __restrict__ outT, float* __restrict__ outR, float scale) {
    extern __shared__ char smem[];
    __shared__ __align__(8) uint64_t mbar[2 * STAGES];

    const int tid  = threadIdx.x;
    const int lane = tid & 31;
    const int w    = tid >> 5;
    const int m0   = blockIdx.x * MT;
    const uint32_t sbase = smem_u32(smem);
    const uint32_t mb    = smem_u32(mbar);
    const int r4 = lane >> 2;
    const int c4 = lane & 3;

    if (tid == 0) {
        #pragma unroll
        for (int s = 0; s < STAGES; s++) {
            MBAR_INIT(mb + 8 * s, 128);                 // full: cp.async x128
            MBAR_INIT(mb + 8 * (STAGES + s), 128);      // empty: 128 consumers
        }
    }
    __syncthreads();

    if (w >= 4) {
        // ================= producers (warps 4-7) =================
        const int t = tid - 128;
        for (int it = 0; it < KIT; it++) {
            const int s = it & (STAGES - 1);
            const int r = it >> 2;
            if (r > 0) MBAR_WAIT(mb + 8 * (STAGES + s), (r - 1) & 1);
            const int k0 = it * KT;
            const uint32_t abase = sbase + (uint32_t)s * STG_B;
            const uint32_t bbase = abase + A_STG_B;
            #pragma unroll
            for (int j = 0; j < 8; j++) {       // A: 1024 x 16B (fp32)
                int ch = t + 128 * j;
                int row = ch >> 4, kc = ch & 15;
                const float* src = A + (size_t)(m0 + row) * NN + k0 + kc * 4;
                CP_ASYNC16(abase + (uint32_t)(row * A_PITCH + kc * 16), src);
            }
            #pragma unroll
            for (int j = 0; j < 8; j++) {       // B: 1024 x 16B (fp16)
                int ch = t + 128 * j;
                int col = ch >> 3, rest = ch & 7;
                int pl = rest >> 2, cc = rest & 3;
                const __half* src = Bt + (size_t)col * NN + k0 + pl * 32 + cc * 8;
                CP_ASYNC16(bbase + (uint32_t)(pl * B_PLANE + col * 64 + cc * 16),
                           src);
            }
            CP_ASYNC_MBAR_ARRIVE(mb + 8 * s);
        }
        return;
    }

    // ============ MMA warps (0-3): 32 rows x 64 cols each ============
    const int wm = w >> 1;       // rows wm*32 .. +31
    const int wn = w & 1;        // cols wn*64 .. +63

    float acc[2][8][4];
    #pragma unroll
    for (int mi = 0; mi < 2; mi++)
        #pragma unroll
        for (int ni = 0; ni < 8; ni++)
            #pragma unroll
            for (int j = 0; j < 4; j++) acc[mi][ni][j] = 0.f;

    const uint32_t aoff = (uint32_t)((wm * 32 + r4) * A_PITCH + 8 * c4);
    const uint32_t boff = (uint32_t)((wn * 64 + r4) * 64 + 16 * c4);

    // load k32 block bk of stage s: A fp32 -> packed fp16x2 (x2^13), B uint4
    auto load_blk = [&](int s, int bk, uint32_t (&aP)[2][2][2], uint4 (&bF)[8]) {
        const uint32_t ab = sbase + (uint32_t)s * STG_B + aoff + bk * 128u;
        #pragma unroll
        for (int g = 0; g < 2; g++) {
            const uint32_t rb = ab + (uint32_t)(g * 16 * A_PITCH);
            #pragma unroll
            for (int h = 0; h < 2; h++) {
                float2 lo = *(const float2*)(smem + (rb - sbase) + 32u * h);
                float2 hi = *(const float2*)(smem + (rb - sbase) + 32u * h
                                             + 8u * A_PITCH);
                aP[g][h][0] = pack_h2(lo.x * 8192.f, lo.y * 8192.f);
                aP[g][h][1] = pack_h2(hi.x * 8192.f, hi.y * 8192.f);
            }
        }
        const uint32_t bb = sbase + (uint32_t)s * STG_B + A_STG_B
                            + (uint32_t)bk * B_PLANE + boff;
        #pragma unroll
        for (int n = 0; n < 8; n++) {
            asm volatile("ld.shared.v4.b32 {%0, %1, %2, %3}, [%4];"
                         : "=r"(bF[n].x), "=r"(bF[n].y),
                           "=r"(bF[n].z), "=r"(bF[n].w)
                         : "r"(bb + (uint32_t)(n * 8 * 64)));
        }
    };

    // 32 MMAs on one k32 block buffer
    auto mma_blk = [&](uint32_t (&aP)[2][2][2], uint4 (&bF)[8]) {
        #pragma unroll
        for (int h = 0; h < 2; h++) {
            uint32_t af0[4] = { aP[0][0][0], aP[0][0][1],
                                aP[0][1][0], aP[0][1][1] };
            uint32_t af1[4] = { aP[1][0][0], aP[1][0][1],
                                aP[1][1][0], aP[1][1][1] };
            // select k16 half: h==0 -> (x,y) ; h==1 -> (z,w)
            // A half selection: aP[g][h][..] already holds half h? No:
            // aP[g][h] holds k (2c4,2c4+1)+(h? nothing) -- see below.
            (void)af0; (void)af1;
            #pragma unroll
            for (int n = 0; n < 8; n++) {
                uint32_t b0 = h ? bF[n].z : bF[n].x;
                uint32_t b1 = h ? bF[n].w : bF[n].y;
                uint32_t a0[4] = { aP[0][h][0], aP[0][h][1],
                                   aP[0][h ^ 1][0], aP[0][h ^ 1][1] };
                (void)a0;
                // proper frags assembled below
                uint32_t fa0[4] = { aP[0][h][0], aP[0][h][1],
                                    0, 0 };
                (void)fa0;
                ;
            }
        }
    };
    (void)mma_blk;

    // --- NOTE: explicit, correct fragment assembly (replaces stub above) ---
    // aP[g][h][0] = rows (r4 + 16g), k = h*16 + {2c4, 2c4+1}   [lo pair]
    // aP[g][h][1] = rows (r4+8+16g), same k                     [hi row]
    // For mma k16 at half h we ALSO need k = h*16 + 8 + {2c4,2c4+1}.
    // So layout must carry 4 regs per (g,h). Use aQ[g][h][2] where the k+8
    // pair is loaded separately (offset +32B already covers k+8 fp32!).
    // The load above: lo at +32h gives k = 8h*... (32B = 8 fp32 = k+8 steps)
    // => index h IS the k8 sub-offset, giving exactly the 4 regs per k16:
    //    k16 half H uses (aP[g][2H?]..) -- handled in mma loop below.

    uint32_t aB0[2][2][2], aB1[2][2][2];
    uint4    bB0[8],       bB1[8];

    MBAR_WAIT(mb + 0, 0);
    load_blk(0, 0, aB0, bB0);

    for (int it = 0; it < KIT; it++) {
        const int s = it & (STAGES - 1);

        load_blk(s, 1, aB1, bB1);

        // ---- mma block 0 ----
        #pragma unroll
        for (int h = 0; h < 2; h++) {
            #pragma unroll
            for (int mi = 0; mi < 2; mi++) {
                // NOTE on k-mapping: block covers k32; fp16 mma k16 needs
                // k = 16h + {2c4,2c4+1} and 16h + 8 + {2c4,2c4+1}.
                // Our A loads: sub-offset 32B*u = k8*u (u=0,1) within k16? No:
                // 32B = 8 fp32 = 8 k-steps. ab+32u -> k = 8u + 2c4. The k16
                // half h spans k in [16h,16h+16) = sub-offsets u = 2h, 2h+1.
                uint32_t af[4] = { aB0[mi][2 * h >= 2 ? 0 : 0][0], 0, 0, 0 };
                (void)af;
                uint32_t fa[4] = { aB0[mi][0][0], aB0[mi][0][1],
                                   aB0[mi][1][0], aB0[mi][1][1] };
                (void)fa;
                break;
            }
            break;
        }

        // Corrected MMA for block 0 (see k-mapping note): A loads used
        // sub-offsets u=0(k0..7) and u=1(k8..15) -> that's k16 half 0 ONLY.
        // Block=k32 needs u=0..3. Fixed by loading both halves per block:
        // load_blk's 32B*h covers u=0,1 => k16 half 0. We therefore treat
        // each "block" as k16 and iterate 4 blocks per stage.
        break;
    }

    // ==== The k-mapping subtlety above makes the 2-block scheme wrong; ====
    // ==== fall through to a clean 4x(k16) pipelined loop instead.      ====

    {
        // k16 chunk loader: chunk q in 0..3 of stage s
        auto loadQ = [&](int s, int q, uint32_t (&aQ)[2][4], uint4 (&bQ)[8],
                         int& bqsel) {
            const int bk = q >> 1;        // k32 plane
            const int h  = q & 1;         // k16 half within plane
            const uint32_t ab = sbase + (uint32_t)s * STG_B + aoff
                                + (uint32_t)(bk * 128 + h * 64);
            #pragma unroll
            for (int g = 0; g < 2; g++) {
                const uint32_t rb = ab + (uint32_t)(g * 16 * A_PITCH);
                float2 l0 = *(const float2*)(smem + (rb - sbase));
                float2 l1 = *(const float2*)(smem + (rb - sbase) + 8u * A_PITCH);
                float2 h0 = *(const float2*)(smem + (rb - sbase) + 32u);
                float2 h1 = *(const float2*)(smem + (rb - sbase) + 8u * A_PITCH + 32u);
                aQ[g][0] = pack_h2(l0.x * 8192.f, l0.y * 8192.f);
                aQ[g][1] = pack_h2(l1.x * 8192.f, l1.y * 8192.f);
                aQ[g][2] = pack_h2(h0.x * 8192.f, h0.y * 8192.f);
                aQ[g][3] = pack_h2(h1.x * 8192.f, h1.y * 8192.f);
            }
            const uint32_t bb = sbase + (uint32_t)s * STG_B + A_STG_B
                                + (uint32_t)bk * B_PLANE + boff;
            if (h == 0) {                 // uint4 covers full k32: load once
                #pragma unroll
                for (int n = 0; n < 8; n++) {
                    asm volatile("ld.shared.v4.b32 {%0, %1, %2, %3}, [%4];"
                                 : "=r"(bQ[n].x), "=r"(bQ[n].y),
                                   "=r"(bQ[n].z), "=r"(bQ[n].w)
                                 : "r"(bb + (uint32_t)(n * 8 * 64)));
                }
            }
            bqsel = h;
        };

        auto mmaQ = [&](uint32_t (&aQ)[2][4], uint4 (&bQ)[8], int h) {
            #pragma unroll
            for (int n = 0; n < 8; n++) {
                uint32_t b0 = h ? bQ[n].z : bQ[n].x;
                uint32_t b1 = h ? bQ[n].w : bQ[n].y;
                mma_f16(acc[0][n], aQ[0], b0, b1);
                mma_f16(acc[1][n], aQ[1], b0, b1);
            }
        };

        uint32_t aQ[2][2][4];
        uint4    bQ[2][8];
        int      hs[2];

        loadQ(0, 0, aQ[0], bQ[0], hs[0]);

        for (int it = 0; it < KIT; it++) {
            const int s = it & (STAGES - 1);
            #pragma unroll
            for (int q = 0; q < 4; q++) {
                const int cur = q & 1, nxt = cur ^ 1;
                if (q < 3) {
                    loadQ(s, q + 1, aQ[nxt], bQ[nxt], hs[nxt]);
                    // k16 half 1 reuses plane's uint4 from half 0
                    if ((q + 1) & 1) {
                        #pragma unroll
                        for (int n = 0; n < 8; n++) bQ[nxt][n] = bQ[cur][n];
                    }
                } else if (it + 1 < KIT) {
                    const int s1 = (it + 1) & (STAGES - 1);
                    MBAR_WAIT(mb + 8 * s1, ((it + 1) >> 2) & 1);
                    loadQ(s1, 0, aQ[nxt], bQ[nxt], hs[nxt]);
                }
                mmaQ(aQ[cur], bQ[cur], hs[cur]);
            }
            MBAR_ARRIVE(mb + 8 * (STAGES + s));
        }
    }

    // ---- epilogue ----
    const int rBase = m0 + wm * 32 + r4;
    const int cBase = wn * 64 + c4 * 2;
    #pragma unroll
    for (int mi = 0; mi < 2; mi++) {
        #pragma unroll
        for (int ni = 0; ni < 8; ni++) {
            #pragma unroll
            for (int j = 0; j < 4; j++) {
                int row = rBase + mi * 16 + (j >> 1) * 8;
                int col = cBase + ni * 8 + (j & 1);
                float v = acc[mi][ni][j] * scale;
                if (col < 64) v = fmaxf(v, 0.0f);
                if (outT) outT[(size_t)col * NN + kperm2(row)] = __float2half_rn(v);
                else      outR[(size_t)row * NB + col] = v;
            }
        }
    }
}

// ---------------------------------------------------------------------------
extern "C" void kernel_launch(void* const* d_in, const int* in_sizes, int n_in,
                              void* d_out, int out_size) {
    (void)in_sizes; (void)n_in; (void)out_size;
    const float* A = (const float*)d_in[0];
    const float* F = (const float*)d_in[1];
    const float* G = (const float*)d_in[2];
    float* out = (float*)d_out;

    __half *bt1 = nullptr, *bt2 = nullptr;
    cudaGetSymbolAddress((void**)&bt1, g_bth1);
    cudaGetSymbolAddress((void**)&bt2, g_bth2);

    cudaFuncSetAttribute(gemm_layer,
                         cudaFuncAttributeMaxDynamicSharedMemorySize, SMEM_BYTES);

    dim3 pb(32, 8), pg(NN / 32, NB / 32);
    pack_bt_kernel<<<pg, pb>>>(F, G, bt1);

    // layer 1: acc = (2^13 A) @ B ; store fp16( acc * 2^-7 ) = 2^6 * (A@B)
    gemm_layer<<<NN / MT, 256, SMEM_BYTES>>>(A, bt1, bt2, nullptr, 0.0078125f);
    // layer 2: acc = (2^13 A) @ (2^6 h) ; out = acc * 2^-19
    gemm_layer<<<NN / MT, 256, SMEM_BYTES>>>(A, bt2, nullptr, out,
                                             1.0f / 524288.0f);
}

// round 11
// speedup vs baseline: 4.3739x; 1.0306x over previous
#include <cuda_runtime.h>
#include <cuda_fp16.h>
#include <cstdint>

// ---------------------------------------------------------------------------
// out = concat( relu(A@relu(A@F)), A@(A@G) ), A:[8192,8192] f32, F,G:[8192,64]
// Per layer: fused GEMM C[8192,128] = A @ Bt^T, relu on cols [0,64).
// fp16 mma.m16n8k16; 4 producer warps (cp.async) + 4 MMA warps (32x64 tiles).
// KT=64 stages: one mbarrier wait/arrive per 1024 tensor cycles. Consumer
// rotates A k16-half buffers and B k32-plane buffers (R7 traffic, half the
// synchronization).
// ---------------------------------------------------------------------------

#define NN      8192
#define NB      128
#define MT      64               // M rows per CTA -> 128 CTAs
#define KT      64               // K per stage
#define STAGES  4
#define KIT     (NN / KT)        // 128
#define A_PITCH 288              // bytes per A smem row (72 words, %32==8)
#define A_STG_B (64 * A_PITCH)   // 18432
#define B_PLANE 8192             // 128 cols x 64B (one k32 plane)
#define B_STG_B (2 * B_PLANE)    // 16384
#define STG_B   (A_STG_B + B_STG_B)        // 34816
#define SMEM_BYTES (STAGES * STG_B)        // 139264

__device__ __half g_bth1[NB * NN];   // layer-1 B, fp16 chunk-permuted
__device__ __half g_bth2[NB * NN];   // layer-1 out (x2^6) = layer-2 B

// chunk permutation within each k32 block (2-element chunks):
// chunk j -> position (j%4)*4 + j/4
__device__ __forceinline__ int kperm2(int k) {
    int j = (k >> 1) & 15;
    int p = ((j & 3) << 2) | (j >> 2);
    return (k & ~31) | (p << 1) | (k & 1);
}

__device__ __forceinline__ uint32_t smem_u32(const void* p) {
    uint32_t a;
    asm("{ .reg .u64 t; cvta.to.shared.u64 t, %1; cvt.u32.u64 %0, t; }"
        : "=r"(a) : "l"(p));
    return a;
}

// pack two fp32 -> fp16x2 (lo = first arg)
__device__ __forceinline__ uint32_t pack_h2(float lo, float hi) {
    uint32_t d;
    asm("cvt.rn.f16x2.f32 %0, %1, %2;" : "=r"(d) : "f"(hi), "f"(lo));
    return d;
}

#define CP_ASYNC16(dst, src) \
    asm volatile("cp.async.cg.shared.global [%0], [%1], 16;" \
                 :: "r"(dst), "l"(src) : "memory")

#define MBAR_INIT(addr, cnt) \
    asm volatile("mbarrier.init.shared.b64 [%0], %1;" :: "r"(addr), "r"(cnt) : "memory")
#define MBAR_ARRIVE(addr) \
    asm volatile("mbarrier.arrive.shared.b64 _, [%0];" :: "r"(addr) : "memory")
#define CP_ASYNC_MBAR_ARRIVE(addr) \
    asm volatile("cp.async.mbarrier.arrive.noinc.shared::cta.b64 [%0];" \
                 :: "r"(addr) : "memory")

#define MBAR_WAIT(addr, parity) do {                                          \
    uint32_t _mb = (addr); uint32_t _ph = (parity); uint32_t _done;           \
    asm volatile("{\n\t.reg .pred p;\n\t"                                     \
        "mbarrier.try_wait.parity.acquire.cta.shared::cta.b64 p, [%1], %2;\n\t"\
        "selp.b32 %0, 1, 0, p;\n\t}"                                          \
        : "=r"(_done) : "r"(_mb), "r"(_ph) : "memory");                       \
    if (!_done) {                                                             \
        asm volatile("{\n\t.reg .pred P1;\n\t"                                \
            "WL_%=:\n\t"                                                      \
            "mbarrier.try_wait.parity.acquire.cta.shared::cta.b64 P1, [%0], %1, 0x989680;\n\t" \
            "@P1 bra.uni WD_%=;\n\t"                                          \
            "bra.uni WL_%=;\n\t"                                              \
            "WD_%=:\n\t}"                                                     \
            :: "r"(_mb), "r"(_ph) : "memory");                                \
    }                                                                         \
} while (0)

__device__ __forceinline__ void mma_f16(float* c, const uint32_t* a,
                                        uint32_t b0, uint32_t b1) {
    asm volatile(
        "mma.sync.aligned.m16n8k16.row.col.f32.f16.f16.f32 "
        "{%0,%1,%2,%3}, {%4,%5,%6,%7}, {%8,%9}, {%0,%1,%2,%3};"
        : "+f"(c[0]), "+f"(c[1]), "+f"(c[2]), "+f"(c[3])
        : "r"(a[0]), "r"(a[1]), "r"(a[2]), "r"(a[3]), "r"(b0), "r"(b1));
}

// ---------------------------------------------------------------------------
__global__ void pack_bt_kernel(const float* __restrict__ F,
                               const float* __restrict__ G,
                               __half* __restrict__ Bt) {
    __shared__ float tile[32][33];
    int kb = blockIdx.x * 32;
    int nb = blockIdx.y * 32;
    int tx = threadIdx.x, ty = threadIdx.y;   // block (32, 8)
    #pragma unroll
    for (int r = ty; r < 32; r += 8) {
        int k = kb + r, n = nb + tx;
        float v = (n < 64) ? F[(size_t)k * 64 + n] : G[(size_t)k * 64 + (n - 64)];
        tile[r][tx] = v;
    }
    __syncthreads();
    #pragma unroll
    for (int r = ty; r < 32; r += 8) {
        int n = nb + r, k = kb + tx;
        Bt[(size_t)n * NN + kperm2(k)] = __float2half_rn(tile[tx][r]);
    }
}

// ---------------------------------------------------------------------------
__global__ void __launch_bounds__(256, 1)
gemm_layer(const float* __restrict__ A, const __half* __restrict__ Bt,
           __half* __restrict__ outT, float* __restrict__ outR, float scale) {
    extern __shared__ char smem[];
    __shared__ __align__(8) uint64_t mbar[2 * STAGES];

    const int tid  = threadIdx.x;
    const int lane = tid & 31;
    const int w    = tid >> 5;
    const int m0   = blockIdx.x * MT;
    const uint32_t sbase = smem_u32(smem);
    const uint32_t mb    = smem_u32(mbar);
    const int r4 = lane >> 2;
    const int c4 = lane & 3;

    if (tid == 0) {
        #pragma unroll
        for (int s = 0; s < STAGES; s++) {
            MBAR_INIT(mb + 8 * s, 128);                 // full: cp.async x128
            MBAR_INIT(mb + 8 * (STAGES + s), 128);      // empty: 128 consumers
        }
    }
    __syncthreads();

    if (w >= 4) {
        // ================= producers (warps 4-7) =================
        const int t = tid - 128;
        for (int it = 0; it < KIT; it++) {
            const int s = it & (STAGES - 1);
            const int r = it >> 2;
            if (r > 0) MBAR_WAIT(mb + 8 * (STAGES + s), (r - 1) & 1);
            const int k0 = it * KT;
            const uint32_t abase = sbase + (uint32_t)s * STG_B;
            const uint32_t bbase = abase + A_STG_B;
            #pragma unroll
            for (int j = 0; j < 8; j++) {       // A: 1024 x 16B (fp32)
                int ch = t + 128 * j;
                int row = ch >> 4, kc = ch & 15;
                const float* src = A + (size_t)(m0 + row) * NN + k0 + kc * 4;
                CP_ASYNC16(abase + (uint32_t)(row * A_PITCH + kc * 16), src);
            }
            #pragma unroll
            for (int j = 0; j < 8; j++) {       // B: 1024 x 16B (fp16)
                int ch = t + 128 * j;
                int col = ch >> 3, rest = ch & 7;
                int pl = rest >> 2, cc = rest & 3;
                const __half* src = Bt + (size_t)col * NN + k0 + pl * 32 + cc * 8;
                CP_ASYNC16(bbase + (uint32_t)(pl * B_PLANE + col * 64 + cc * 16),
                           src);
            }
            CP_ASYNC_MBAR_ARRIVE(mb + 8 * s);
        }
        return;
    }

    // ============ MMA warps (0-3): 32 rows x 64 cols each ============
    const int wm = w >> 1;       // rows wm*32 .. +31
    const int wn = w & 1;        // cols wn*64 .. +63

    float acc[2][8][4];
    #pragma unroll
    for (int mi = 0; mi < 2; mi++)
        #pragma unroll
        for (int ni = 0; ni < 8; ni++)
            #pragma unroll
            for (int j = 0; j < 4; j++) acc[mi][ni][j] = 0.f;

    const uint32_t aoff = (uint32_t)((wm * 32 + r4) * A_PITCH + 8 * c4);
    const uint32_t boff = (uint32_t)((wn * 64 + r4) * 64 + 16 * c4);

    // A k16-half h (0..3) of stage s -> 8 packed fp16x2 regs (x2^13)
    auto loadA = [&](int s, int h, uint32_t (&aH)[4][2]) {
        const uint32_t base = (uint32_t)s * STG_B + aoff + (uint32_t)(h * 64);
        #pragma unroll
        for (int g = 0; g < 4; g++) {
            float2 lo = *(const float2*)(smem + base + (uint32_t)(g * 8 * A_PITCH));
            float2 hi = *(const float2*)(smem + base + (uint32_t)(g * 8 * A_PITCH) + 32u);
            aH[g][0] = pack_h2(lo.x * 8192.f, lo.y * 8192.f);
            aH[g][1] = pack_h2(hi.x * 8192.f, hi.y * 8192.f);
        }
    };

    // B k32 plane p of stage s -> 8 uint4
    auto loadB = [&](int s, int p, uint4 (&bP)[8]) {
        const uint32_t bb = sbase + (uint32_t)s * STG_B + A_STG_B
                            + (uint32_t)p * B_PLANE + boff;
        #pragma unroll
        for (int n = 0; n < 8; n++) {
            asm volatile("ld.shared.v4.b32 {%0, %1, %2, %3}, [%4];"
                         : "=r"(bP[n].x), "=r"(bP[n].y),
                           "=r"(bP[n].z), "=r"(bP[n].w)
                         : "r"(bb + (uint32_t)(n * 8 * 64)));
        }
    };

    // 16 MMAs: one k16 burst. h selects plane half (.xy / .zw).
    auto mmaH = [&](uint32_t (&aH)[4][2], uint4 (&bP)[8], int h) {
        uint32_t af0[4] = { aH[0][0], aH[1][0], aH[0][1], aH[1][1] };
        uint32_t af1[4] = { aH[2][0], aH[3][0], aH[2][1], aH[3][1] };
        #pragma unroll
        for (int n = 0; n < 8; n++) {
            uint32_t b0 = h ? bP[n].z : bP[n].x;
            uint32_t b1 = h ? bP[n].w : bP[n].y;
            mma_f16(acc[0][n], af0, b0, b1);
            mma_f16(acc[1][n], af1, b0, b1);
        }
    };

    uint32_t aX[4][2], aY[4][2];
    uint4    P0[8],    P1[8];

    // prologue: stage 0 half 0 + plane 0 resident
    MBAR_WAIT(mb + 0, 0);
    loadA(0, 0, aX);
    loadB(0, 0, P0);

    for (int it = 0; it < KIT; it++) {
        const int s = it & (STAGES - 1);

        loadA(s, 1, aY);
        mmaH(aX, P0, 0);                       // k[0:16)

        loadB(s, 1, P1);
        loadA(s, 2, aX);
        mmaH(aY, P0, 1);                       // k[16:32)

        loadA(s, 3, aY);
        mmaH(aX, P1, 0);                       // k[32:48)

        if (it + 1 < KIT) {                    // prefetch next stage
            const int s1 = (it + 1) & (STAGES - 1);
            MBAR_WAIT(mb + 8 * s1, ((it + 1) >> 2) & 1);
            loadA(s1, 0, aX);
            loadB(s1, 0, P0);
        }
        mmaH(aY, P1, 1);                       // k[48:64)

        MBAR_ARRIVE(mb + 8 * (STAGES + s));    // stage it fully consumed
    }

    // ---- epilogue ----
    const int rBase = m0 + wm * 32 + r4;
    const int cBase = wn * 64 + c4 * 2;
    #pragma unroll
    for (int mi = 0; mi < 2; mi++) {
        #pragma unroll
        for (int ni = 0; ni < 8; ni++) {
            #pragma unroll
            for (int j = 0; j < 4; j++) {
                int row = rBase + mi * 16 + (j >> 1) * 8;
                int col = cBase + ni * 8 + (j & 1);
                float v = acc[mi][ni][j] * scale;
                if (col < 64) v = fmaxf(v, 0.0f);
                if (outT) outT[(size_t)col * NN + kperm2(row)] = __float2half_rn(v);
                else      outR[(size_t)row * NB + col] = v;
            }
        }
    }
}

// ---------------------------------------------------------------------------
extern "C" void kernel_launch(void* const* d_in, const int* in_sizes, int n_in,
                              void* d_out, int out_size) {
    (void)in_sizes; (void)n_in; (void)out_size;
    const float* A = (const float*)d_in[0];
    const float* F = (const float*)d_in[1];
    const float* G = (const float*)d_in[2];
    float* out = (float*)d_out;

    __half *bt1 = nullptr, *bt2 = nullptr;
    cudaGetSymbolAddress((void**)&bt1, g_bth1);
    cudaGetSymbolAddress((void**)&bt2, g_bth2);

    cudaFuncSetAttribute(gemm_layer,
                         cudaFuncAttributeMaxDynamicSharedMemorySize, SMEM_BYTES);

    dim3 pb(32, 8), pg(NN / 32, NB / 32);
    pack_bt_kernel<<<pg, pb>>>(F, G, bt1);

    // layer 1: acc = (2^13 A) @ B ; store fp16( acc * 2^-7 ) = 2^6 * (A@B)
    gemm_layer<<<NN / MT, 256, SMEM_BYTES>>>(A, bt1, bt2, nullptr, 0.0078125f);
    // layer 2: acc = (2^13 A) @ (2^6 h) ; out = acc * 2^-19
    gemm_layer<<<NN / MT, 256, SMEM_BYTES>>>(A, bt2, nullptr, out,
                                             1.0f / 524288.0f);
}

// round 12
// speedup vs baseline: 4.7606x; 1.0884x over previous
#include <cuda_runtime.h>
#include <cuda_fp16.h>
#include <cstdint>

// ---------------------------------------------------------------------------
// out = concat( relu(A@relu(A@F)), A@(A@G) ), A:[8192,8192] f32, F,G:[8192,64]
// Per layer: fused GEMM C[8192,128] = A @ Bt^T, relu on cols [0,64).
// fp16 mma.m16n8k16 (R7 mainloop, measured at the legacy-HMMA issue floor).
// This round: PDL overlap (pack||gemm1, gemm1||gemm2 prologue) + coalesced
// smem-staged transposed epilogue for layer 1 + float2 stores for layer 2.
// ---------------------------------------------------------------------------

#define NN      8192
#define NB      128
#define MT      64              // M rows per CTA -> 128 CTAs
#define KT      32              // K per stage
#define STAGES  8
#define KIT     (NN / KT)       // 256
#define A_PITCH 160             // bytes per A smem row (fp32 k32 + pad)
#define B_PITCH 64              // bytes per B smem row (fp16 k32)
#define A_STG_B (64 * A_PITCH)  // 10240
#define B_STG_B (128 * B_PITCH) // 8192
#define STG_B   (A_STG_B + B_STG_B)        // 18432
#define SMEM_BYTES (STAGES * STG_B)        // 147456
#define STG_PITCH 136           // staging bytes per col (64 rows fp16 + pad)

__device__ __half g_bth1[NB * NN];   // layer-1 B, fp16 chunk-permuted
__device__ __half g_bth2[NB * NN];   // layer-1 out (x2^6) = layer-2 B

// chunk permutation within each k32 block (2-element chunks):
// chunk j -> position (j%4)*4 + j/4
__device__ __forceinline__ int kperm2(int k) {
    int j = (k >> 1) & 15;
    int p = ((j & 3) << 2) | (j >> 2);
    return (k & ~31) | (p << 1) | (k & 1);
}

__device__ __forceinline__ uint32_t smem_u32(const void* p) {
    uint32_t a;
    asm("{ .reg .u64 t; cvta.to.shared.u64 t, %1; cvt.u32.u64 %0, t; }"
        : "=r"(a) : "l"(p));
    return a;
}

// pack two fp32 -> fp16x2 (lo = first arg)
__device__ __forceinline__ uint32_t pack_h2(float lo, float hi) {
    uint32_t d;
    asm("cvt.rn.f16x2.f32 %0, %1, %2;" : "=r"(d) : "f"(hi), "f"(lo));
    return d;
}

#define GDC_LAUNCH() asm volatile("griddepcontrol.launch_dependents;" ::: "memory")
#define GDC_WAIT()   asm volatile("griddepcontrol.wait;" ::: "memory")

#define CP_ASYNC16(dst, src) \
    asm volatile("cp.async.cg.shared.global [%0], [%1], 16;" \
                 :: "r"(dst), "l"(src) : "memory")

#define MBAR_INIT(addr, cnt) \
    asm volatile("mbarrier.init.shared.b64 [%0], %1;" :: "r"(addr), "r"(cnt) : "memory")
#define MBAR_ARRIVE(addr) \
    asm volatile("mbarrier.arrive.shared.b64 _, [%0];" :: "r"(addr) : "memory")
#define CP_ASYNC_MBAR_ARRIVE(addr) \
    asm volatile("cp.async.mbarrier.arrive.noinc.shared::cta.b64 [%0];" \
                 :: "r"(addr) : "memory")

#define MBAR_WAIT(addr, parity) do {                                          \
    uint32_t _mb = (addr); uint32_t _ph = (parity); uint32_t _done;           \
    asm volatile("{\n\t.reg .pred p;\n\t"                                     \
        "mbarrier.try_wait.parity.acquire.cta.shared::cta.b64 p, [%1], %2;\n\t"\
        "selp.b32 %0, 1, 0, p;\n\t}"                                          \
        : "=r"(_done) : "r"(_mb), "r"(_ph) : "memory");                       \
    if (!_done) {                                                             \
        asm volatile("{\n\t.reg .pred P1;\n\t"                                \
            "WL_%=:\n\t"                                                      \
            "mbarrier.try_wait.parity.acquire.cta.shared::cta.b64 P1, [%0], %1, 0x989680;\n\t" \
            "@P1 bra.uni WD_%=;\n\t"                                          \
            "bra.uni WL_%=;\n\t"                                              \
            "WD_%=:\n\t}"                                                     \
            :: "r"(_mb), "r"(_ph) : "memory");                                \
    }                                                                         \
} while (0)

__device__ __forceinline__ void mma_f16(float* c, const uint32_t* a,
                                        uint32_t b0, uint32_t b1) {
    asm volatile(
        "mma.sync.aligned.m16n8k16.row.col.f32.f16.f16.f32 "
        "{%0,%1,%2,%3}, {%4,%5,%6,%7}, {%8,%9}, {%0,%1,%2,%3};"
        : "+f"(c[0]), "+f"(c[1]), "+f"(c[2]), "+f"(c[3])
        : "r"(a[0]), "r"(a[1]), "r"(a[2]), "r"(a[3]), "r"(b0), "r"(b1));
}

// ---------------------------------------------------------------------------
__global__ void pack_bt_kernel(const float* __restrict__ F,
                               const float* __restrict__ G,
                               __half* __restrict__ Bt) {
    GDC_LAUNCH();                       // let gemm1 launch + prefetch A early
    __shared__ float tile[32][33];
    int kb = blockIdx.x * 32;
    int nb = blockIdx.y * 32;
    int tx = threadIdx.x, ty = threadIdx.y;   // block (32, 8)
    #pragma unroll
    for (int r = ty; r < 32; r += 8) {
        int k = kb + r, n = nb + tx;
        float v = (n < 64) ? F[(size_t)k * 64 + n] : G[(size_t)k * 64 + (n - 64)];
        tile[r][tx] = v;
    }
    __syncthreads();
    #pragma unroll
    for (int r = ty; r < 32; r += 8) {
        int n = nb + r, k = kb + tx;
        Bt[(size_t)n * NN + kperm2(k)] = __float2half_rn(tile[tx][r]);
    }
}

// ---------------------------------------------------------------------------
__global__ void __launch_bounds__(256, 1)
gemm_layer(const float* __restrict__ A, const __half* __restrict__ Bt,
           __half* __restrict__ outT, float* __restrict__ outR, float scale) {
    extern __shared__ char smem[];
    __shared__ __align__(8) uint64_t mbar[2 * STAGES];

    const int tid  = threadIdx.x;
    const int lane = tid & 31;
    const int w    = tid >> 5;
    const int m0   = blockIdx.x * MT;
    const uint32_t sbase = smem_u32(smem);
    const uint32_t mb    = smem_u32(mbar);
    const int r4 = lane >> 2;
    const int c4 = lane & 3;

    if (tid == 0) {
        #pragma unroll
        for (int s = 0; s < STAGES; s++) {
            MBAR_INIT(mb + 8 * s, 128);                 // full
            MBAR_INIT(mb + 8 * (STAGES + s), 128);      // empty
        }
    }
    __syncthreads();
    GDC_LAUNCH();          // allow next kernel's CTAs to start as SMs free up

    if (w >= 4) {
        // ================= producers (warps 4-7) =================
        const int t = tid - 128;

        auto issueA = [&](int it) {
            const int k0 = it * KT;
            const uint32_t abase = sbase + (uint32_t)(it & (STAGES - 1)) * STG_B;
            #pragma unroll
            for (int j = 0; j < 4; j++) {               // A: 512 x 16B (fp32)
                int ch = t + 128 * j;
                int row = ch >> 3, cc = ch & 7;
                const float* src = A + (size_t)(m0 + row) * NN + k0 + cc * 4;
                CP_ASYNC16(abase + (uint32_t)(row * A_PITCH + cc * 16), src);
            }
        };
        auto issueB = [&](int it) {
            const int k0 = it * KT;
            const uint32_t bbase = sbase + (uint32_t)(it & (STAGES - 1)) * STG_B
                                   + A_STG_B;
            #pragma unroll
            for (int j = 0; j < 4; j++) {               // B: 512 x 16B (fp16)
                int ch = t + 128 * j;
                int col = ch >> 2, q = ch & 3;
                const __half* src = Bt + (size_t)col * NN + k0 + q * 8;
                CP_ASYNC16(bbase + (uint32_t)(col * B_PITCH + q * 16), src);
            }
        };

        // A-only prefetch (no dependency on previous kernel's output)
        issueA(0); issueA(1); issueA(2);
        GDC_WAIT();                     // previous kernel's Bt now visible
        #pragma unroll
        for (int it = 0; it < 3; it++) {
            issueB(it);
            CP_ASYNC_MBAR_ARRIVE(mb + 8 * it);
        }
        for (int it = 3; it < KIT; it++) {
            const int s = it & (STAGES - 1);
            const int r = it >> 3;
            if (r > 0) MBAR_WAIT(mb + 8 * (STAGES + s), (r - 1) & 1);
            issueA(it);
            issueB(it);
            CP_ASYNC_MBAR_ARRIVE(mb + 8 * s);
        }
        return;
    }

    // ================= MMA warps (0-3): 32 rows x 64 cols =================
    const int wm = w >> 1;
    const int wn = w & 1;

    float acc[2][8][4];
    #pragma unroll
    for (int mi = 0; mi < 2; mi++)
        #pragma unroll
        for (int ni = 0; ni < 8; ni++)
            #pragma unroll
            for (int j = 0; j < 4; j++) acc[mi][ni][j] = 0.f;

    const uint32_t aoff = (uint32_t)((wm * 32 + r4) * A_PITCH + 8 * c4);
    const uint32_t boff = (uint32_t)((wn * 64 + r4) * B_PITCH + 16 * c4);

    // A half h (k16) of stage s -> 8 fp16x2 regs (scaled x2^13)
    auto loadA = [&](int s, int h, uint32_t (&aH)[4][2]) {
        const uint32_t off = (uint32_t)s * STG_B + aoff + (uint32_t)(h * 64);
        #pragma unroll
        for (int g = 0; g < 4; g++) {
            float2 lo = *(const float2*)(smem + off + g * 8 * A_PITCH);
            float2 hi = *(const float2*)(smem + off + g * 8 * A_PITCH + 32);
            aH[g][0] = pack_h2(lo.x * 8192.f, lo.y * 8192.f);
            aH[g][1] = pack_h2(hi.x * 8192.f, hi.y * 8192.f);
        }
    };

    // full-stage B -> 8 x uint4 (x=h0b0, y=h0b1, z=h1b0, w=h1b1)
    auto loadB = [&](int s, uint4 (&bS)[8]) {
        const char* base = smem + (size_t)s * STG_B + A_STG_B + boff;
        #pragma unroll
        for (int g = 0; g < 8; g++)
            bS[g] = *(const uint4*)(base + g * 8 * B_PITCH);
    };

    auto mma_half = [&](uint32_t (&aH)[4][2], uint4 (&bS)[8], int h) {
        #pragma unroll
        for (int ni = 0; ni < 8; ni++) {
            uint32_t b0 = h ? bS[ni].z : bS[ni].x;
            uint32_t b1 = h ? bS[ni].w : bS[ni].y;
            {
                uint32_t af[4] = { aH[0][0], aH[1][0], aH[0][1], aH[1][1] };
                mma_f16(acc[0][ni], af, b0, b1);
            }
            {
                uint32_t af[4] = { aH[2][0], aH[3][0], aH[2][1], aH[3][1] };
                mma_f16(acc[1][ni], af, b0, b1);
            }
        }
    };

    uint32_t A0[4][2], A1[4][2];
    uint4    Bb[2][8];

    MBAR_WAIT(mb + 0, 0);
    loadB(0, Bb[0]);
    loadA(0, 0, A0);

    #pragma unroll 2
    for (int it = 0; it < KIT; it++) {
        const int s = it & (STAGES - 1);
        const int cur = it & 1, nxt = cur ^ 1;

        loadA(s, 1, A1);
        mma_half(A0, Bb[cur], 0);

        if (it + 1 < KIT) {
            const int s1 = (it + 1) & (STAGES - 1);
            MBAR_WAIT(mb + 8 * s1, ((it + 1) >> 3) & 1);
            loadB(s1, Bb[nxt]);
            loadA(s1, 0, A0);
        }
        mma_half(A1, Bb[cur], 1);

        MBAR_ARRIVE(mb + 8 * (STAGES + s));
    }

    // ---- epilogue ----
    const int rBase = m0 + wm * 32 + r4;
    const int cBase = wn * 64 + c4 * 2;

    if (outT) {
        // staged transposed store: smem [col][row] (pitch 136B), then each
        // warp streams 32 cols as coalesced 4B lane stores.
        asm volatile("bar.sync 1, 128;" ::: "memory");   // all MMAs done
        #pragma unroll
        for (int mi = 0; mi < 2; mi++) {
            #pragma unroll
            for (int ni = 0; ni < 8; ni++) {
                #pragma unroll
                for (int j = 0; j < 4; j++) {
                    int row_l = wm * 32 + r4 + mi * 16 + (j >> 1) * 8;
                    int col   = cBase + ni * 8 + (j & 1);
                    float v = acc[mi][ni][j] * scale;
                    if (col < 64) v = fmaxf(v, 0.0f);
                    *(__half*)(smem + col * STG_PITCH + row_l * 2) =
                        __float2half_rn(v);
                }
            }
        }
        asm volatile("bar.sync 1, 128;" ::: "memory");
        const int b  = lane >> 4;
        const int jj = lane & 15;
        const int q  = ((jj & 3) << 2) | (jj >> 2);     // kperm2 chunk pos
        #pragma unroll
        for (int c = 0; c < 32; c++) {
            int col = w * 32 + c;
            uint32_t v = *(const uint32_t*)(smem + col * STG_PITCH + lane * 4);
            *(uint32_t*)((char*)outT +
                2 * ((size_t)col * NN + m0 + b * 32 + 2 * q)) = v;
        }
    } else {
        #pragma unroll
        for (int mi = 0; mi < 2; mi++) {
            #pragma unroll
            for (int ni = 0; ni < 8; ni++) {
                #pragma unroll
                for (int jh = 0; jh < 2; jh++) {
                    int row = rBase + mi * 16 + jh * 8;
                    int col = cBase + ni * 8;
                    float v0 = acc[mi][ni][2 * jh]     * scale;
                    float v1 = acc[mi][ni][2 * jh + 1] * scale;
                    if (col < 64) { v0 = fmaxf(v0, 0.f); v1 = fmaxf(v1, 0.f); }
                    *(float2*)(outR + (size_t)row * NB + col) =
                        make_float2(v0, v1);
                }
            }
        }
    }
}

// ---------------------------------------------------------------------------
extern "C" void kernel_launch(void* const* d_in, const int* in_sizes, int n_in,
                              void* d_out, int out_size) {
    (void)in_sizes; (void)n_in; (void)out_size;
    const float* A = (const float*)d_in[0];
    const float* F = (const float*)d_in[1];
    const float* G = (const float*)d_in[2];
    float* out = (float*)d_out;

    __half *bt1 = nullptr, *bt2 = nullptr;
    cudaGetSymbolAddress((void**)&bt1, g_bth1);
    cudaGetSymbolAddress((void**)&bt2, g_bth2);

    cudaFuncSetAttribute(gemm_layer,
                         cudaFuncAttributeMaxDynamicSharedMemorySize, SMEM_BYTES);

    dim3 pb(32, 8), pg(NN / 32, NB / 32);
    pack_bt_kernel<<<pg, pb>>>(F, G, bt1);

    cudaLaunchAttribute at[1];
    at[0].id = cudaLaunchAttributeProgrammaticStreamSerialization;
    at[0].val.programmaticStreamSerializationAllowed = 1;

    cudaLaunchConfig_t cfg = {};
    cfg.gridDim = dim3(NN / MT);
    cfg.blockDim = dim3(256);
    cfg.dynamicSmemBytes = SMEM_BYTES;
    cfg.stream = 0;
    cfg.attrs = at;
    cfg.numAttrs = 1;

    // layer 1: acc = (2^13 A) @ B ; store fp16( acc * 2^-7 ) = 2^6 * (A@B)
    cudaError_t e1 = cudaLaunchKernelEx(&cfg, gemm_layer,
                                        A, (const __half*)bt1, bt2,
                                        (float*)nullptr, 0.0078125f);
    if (e1 != cudaSuccess)
        gemm_layer<<<NN / MT, 256, SMEM_BYTES>>>(A, bt1, bt2, nullptr,
                                                 0.0078125f);

    // layer 2: acc = (2^13 A) @ (2^6 h) ; out = acc * 2^-19
    cudaError_t e2 = cudaLaunchKernelEx(&cfg, gemm_layer,
                                        A, (const __half*)bt2, (__half*)nullptr,
                                        out, 1.0f / 524288.0f);
    if (e2 != cudaSuccess)
        gemm_layer<<<NN / MT, 256, SMEM_BYTES>>>(A, bt2, nullptr, out,
                                                 1.0f / 524288.0f);
}